// round 6
// baseline (speedup 1.0000x reference)
#include <cuda_runtime.h>
#include <math.h>
#include <stdint.h>

// ---------------- static device scratch (no allocation allowed) ----------------
__device__ float    g_xg1 [(size_t)32768 * 1024];   // layer1 input projection, layout [b][t][j*4+g]
__device__ float    g_out1[(size_t)32768 * 256];    // layer1 hidden outputs [b][t][j] (tf32-rounded)
__device__ float    g_xg2 [(size_t)32768 * 512];    // layer2 input projection [b][t][j*4+g]
__device__ float    g_w1cv[(size_t)1024 * 2048];    // Wih1 rounded to tf32
__device__ float    g_w2cv[(size_t)512 * 256];      // Wih2 rounded to tf32
__device__ float    g_h2f [64 * 128];               // final layer2 h

// ---------------- helpers ----------------
__device__ __forceinline__ unsigned f2tf32(float f) {
    unsigned r;
    asm("cvt.rna.tf32.f32 %0, %1;" : "=r"(r) : "f"(f));
    return r;
}

__device__ __forceinline__ void mma_tf32(float* c, const unsigned* a, const unsigned* b) {
    asm volatile(
        "mma.sync.aligned.m16n8k8.row.col.f32.tf32.tf32.f32 "
        "{%0,%1,%2,%3},{%4,%5,%6,%7},{%8,%9},{%0,%1,%2,%3};"
        : "+f"(c[0]), "+f"(c[1]), "+f"(c[2]), "+f"(c[3])
        : "r"(a[0]), "r"(a[1]), "r"(a[2]), "r"(a[3]), "r"(b[0]), "r"(b[1]));
}

__device__ __forceinline__ void cp_async16(void* smem_dst, const void* gptr) {
    unsigned s = (unsigned)__cvta_generic_to_shared(smem_dst);
    asm volatile("cp.async.cg.shared.global [%0], [%1], 16;\n" :: "r"(s), "l"(gptr));
}
#define CP_COMMIT() asm volatile("cp.async.commit_group;\n" ::: "memory")
#define CP_WAIT0()  asm volatile("cp.async.wait_group 0;\n" ::: "memory")

__device__ __forceinline__ uint32_t smem_u32(const void* p) {
    return (uint32_t)__cvta_generic_to_shared(p);
}
__device__ __forceinline__ uint32_t my_ctarank() {
    uint32_t r;
    asm("mov.u32 %0, %%cluster_ctarank;" : "=r"(r));
    return r;
}
#define CLUSTER_ARRIVE() asm volatile("barrier.cluster.arrive.aligned;" ::: "memory")
#define CLUSTER_WAIT()   asm volatile("barrier.cluster.wait.aligned;" ::: "memory")

// fast precise activations (MUFU ex2 + rcp; err ~1e-6)
__device__ __forceinline__ float fsigmoid(float x) {
    return 1.f / (1.f + __expf(-x));
}
__device__ __forceinline__ float ftanh(float x) {
    return 1.f - 2.f / (1.f + __expf(2.f * x));
}

// ---------------- prep: round weights to tf32 once ----------------
__global__ void cvt_rna_kernel(const float* __restrict__ src, float* __restrict__ dst, int n) {
    int i = blockIdx.x * 256 + threadIdx.x;
    if (i < n) dst[i] = __uint_as_float(f2tf32(src[i]));
}

// ---------------- tf32 GEMM with permuted output columns (unchanged) ----------------
__global__ void __launch_bounds__(256, 2) gemm_tf32_perm(
    const float* __restrict__ A, const float* __restrict__ W,
    const float* __restrict__ b1, const float* __restrict__ b2,
    float* __restrict__ C, int M, int N, int K)
{
    extern __shared__ unsigned sh[];
    unsigned* As = sh;                 // [2][128][36]
    unsigned* Bs = sh + 2 * 128 * 36;  // [2][128][36]

    const int tid = threadIdx.x, lane = tid & 31, warp = tid >> 5;
    const int wm = warp & 1, wn = warp >> 1;
    const int g = lane >> 2, tg = lane & 3;
    const int bn = blockIdx.x * 128, bm = blockIdx.y * 128;
    const int H = N >> 2;

    float acc[4][4][4];
#pragma unroll
    for (int a = 0; a < 4; a++)
#pragma unroll
        for (int b = 0; b < 4; b++)
#pragma unroll
            for (int c = 0; c < 4; c++) acc[a][b][c] = 0.f;

    const int NK = K >> 5;

#pragma unroll
    for (int i = 0; i < 4; i++) {
        int id = tid + i * 256, row = id >> 3, c4 = id & 7;
        cp_async16(&As[row * 36 + c4 * 4], A + (size_t)(bm + row) * K + c4 * 4);
        int np = bn + row;
        int srow = (np & 3) * H + (np >> 2);
        cp_async16(&Bs[row * 36 + c4 * 4], W + (size_t)srow * K + c4 * 4);
    }
    CP_COMMIT();

    int buf = 0;
    for (int kt = 0; kt < NK; kt++) {
        CP_WAIT0();
        __syncthreads();
        if (kt + 1 < NK) {
            int koff = (kt + 1) * 32;
            int nb = buf ^ 1;
#pragma unroll
            for (int i = 0; i < 4; i++) {
                int id = tid + i * 256, row = id >> 3, c4 = id & 7;
                cp_async16(&As[nb * 128 * 36 + row * 36 + c4 * 4],
                           A + (size_t)(bm + row) * K + koff + c4 * 4);
                int np = bn + row;
                int srow = (np & 3) * H + (np >> 2);
                cp_async16(&Bs[nb * 128 * 36 + row * 36 + c4 * 4],
                           W + (size_t)srow * K + koff + c4 * 4);
            }
        }
        CP_COMMIT();

        const unsigned* Ab = As + buf * 128 * 36;
        const unsigned* Bb = Bs + buf * 128 * 36;
#pragma unroll
        for (int ks = 0; ks < 4; ks++) {
            unsigned af[4][4], bf[4][2];
#pragma unroll
            for (int mt = 0; mt < 4; mt++) {
                int r = wm * 64 + mt * 16 + g;
                af[mt][0] = Ab[r * 36 + ks * 8 + tg];
                af[mt][1] = Ab[(r + 8) * 36 + ks * 8 + tg];
                af[mt][2] = Ab[r * 36 + ks * 8 + tg + 4];
                af[mt][3] = Ab[(r + 8) * 36 + ks * 8 + tg + 4];
            }
#pragma unroll
            for (int nt = 0; nt < 4; nt++) {
                int nl = wn * 32 + nt * 8 + g;
                bf[nt][0] = Bb[nl * 36 + ks * 8 + tg];
                bf[nt][1] = Bb[nl * 36 + ks * 8 + tg + 4];
            }
#pragma unroll
            for (int mt = 0; mt < 4; mt++)
#pragma unroll
                for (int nt = 0; nt < 4; nt++)
                    mma_tf32(acc[mt][nt], af[mt], bf[nt]);
        }
        buf ^= 1;
    }

#pragma unroll
    for (int mt = 0; mt < 4; mt++) {
        int r0 = bm + wm * 64 + mt * 16 + g;
#pragma unroll
        for (int nt = 0; nt < 4; nt++) {
            int c = bn + wn * 32 + nt * 8 + tg * 2;
            int s0 = (c & 3) * H + (c >> 2);
            int s1 = ((c + 1) & 3) * H + ((c + 1) >> 2);
            float bb0 = b1[s0] + b2[s0];
            float bb1 = b1[s1] + b2[s1];
            C[(size_t)r0 * N + c]           = acc[mt][nt][0] + bb0;
            C[(size_t)r0 * N + c + 1]       = acc[mt][nt][1] + bb1;
            C[(size_t)(r0 + 8) * N + c]     = acc[mt][nt][2] + bb0;
            C[(size_t)(r0 + 8) * N + c + 1] = acc[mt][nt][3] + bb1;
        }
    }
}

// ---------------- cluster-based LSTM recurrence v2 ----------------
// Grid: 8 batch-groups x cluster of 8 CTAs. Cluster rank owns JPC hidden units.
// Weights in registers. Per step:
//   MMA (4 acc chains) -> part smem -> sync -> per-(b,unit) update, h staged
//   locally -> sync -> cooperative float4 DSMEM broadcast to 7 peers ->
//   cluster.arrive -> prefetch xg(t+1) -> cluster.wait.
template <int HD, int JPC, int NT, bool STORE_OUT>
__global__ void __launch_bounds__(NT, 1) __cluster_dims__(8, 1, 1)
lstm_recur_cl2(const float* __restrict__ xg,    // [b][t][j*4+g]
               const float* __restrict__ Whh,   // [4*HD][HD]
               float* __restrict__ out,         // [b][t][HD] (layer1) or null
               float* __restrict__ hfin,        // [64][HD] final h (layer2) or null
               int T)
{
    constexpr int KS  = HD / 8;        // mma k-steps
    constexpr int HDP = HD + 4;        // padded h row stride
    constexpr int RP  = 4 * JPC + 4;   // padded partial row stride
    constexpr int NG  = JPC / 4;       // float4 per batch in own slice
    constexpr int CPY = 7 * 8 * NG;    // remote float4 copies per step

    extern __shared__ unsigned smem_u[];
    unsigned* hs = smem_u;                       // [2][8][HDP] tf32 h
    float* part  = (float*)(hs + 2 * 8 * HDP);   // [8][RP]

    const int tid = threadIdx.x, lane = tid & 31, warp = tid >> 5;
    const int g = lane >> 2, tg = lane & 3;
    const uint32_t rank = my_ctarank();
    const int bg = blockIdx.x >> 3;
    const int jbase = (int)rank * JPC;
    const int bglob0 = bg * 8;

    // ---- preload weight fragments into registers (once) ----
    unsigned areg[KS][4];
    {
        int lr0 = warp * 16 + g, lr1 = lr0 + 8;
        const float* w0 = Whh + (size_t)((lr0 & 3) * HD + jbase + (lr0 >> 2)) * HD;
        const float* w1 = Whh + (size_t)((lr1 & 3) * HD + jbase + (lr1 >> 2)) * HD;
#pragma unroll
        for (int ks = 0; ks < KS; ks++) {
            areg[ks][0] = f2tf32(w0[ks * 8 + tg]);
            areg[ks][1] = f2tf32(w1[ks * 8 + tg]);
            areg[ks][2] = f2tf32(w0[ks * 8 + tg + 4]);
            areg[ks][3] = f2tf32(w1[ks * 8 + tg + 4]);
        }
    }

    // zero both h buffers
    for (int i = tid; i < 2 * 8 * HDP; i += NT) hs[i] = 0u;
    __syncthreads();
    CLUSTER_ARRIVE();
    CLUSTER_WAIT();

    // updater mapping: one (batch, unit) per thread (NT == 8*JPC)
    const int b  = tid / JPC;
    const int jl = tid % JPC;
    const float* xgp = xg + ((size_t)(bglob0 + b) * T) * (4 * HD) + (jbase + jl) * 4;
    const uint32_t hs_base = smem_u32(hs);
    float cc = 0.f;
    float4 xv = *(const float4*)xgp;   // step 0 gates

    for (int t = 0; t < T; t++) {
        const int rb = t & 1, wb = rb ^ 1;

        // ---- mma: rows [warp*16,+16) x 8 batches, 4 accumulator chains ----
        {
            float acc[4][4];
#pragma unroll
            for (int ch = 0; ch < 4; ch++)
#pragma unroll
                for (int i = 0; i < 4; i++) acc[ch][i] = 0.f;

            const unsigned* hb = hs + rb * 8 * HDP + g * HDP;  // batch g
#pragma unroll
            for (int ks = 0; ks < KS; ks++) {
                unsigned bf[2];
                bf[0] = hb[ks * 8 + tg];
                bf[1] = hb[ks * 8 + tg + 4];
                mma_tf32(acc[ks & 3], areg[ks], bf);
            }
            float s0 = (acc[0][0] + acc[1][0]) + (acc[2][0] + acc[3][0]);
            float s1 = (acc[0][1] + acc[1][1]) + (acc[2][1] + acc[3][1]);
            float s2 = (acc[0][2] + acc[1][2]) + (acc[2][2] + acc[3][2]);
            float s3 = (acc[0][3] + acc[1][3]) + (acc[2][3] + acc[3][3]);
            int lr = warp * 16 + g;
            part[(tg * 2 + 0) * RP + lr]     = s0;
            part[(tg * 2 + 1) * RP + lr]     = s1;
            part[(tg * 2 + 0) * RP + lr + 8] = s2;
            part[(tg * 2 + 1) * RP + lr + 8] = s3;
        }
        __syncthreads();

        // ---- update one (batch, unit); stage h locally ----
        {
            float4 p = *(const float4*)(part + b * RP + jl * 4);  // gates i,f,c,o
            float iv = fsigmoid(p.x + xv.x);
            float fv = fsigmoid(p.y + xv.y);
            float gv = ftanh(p.z + xv.z);
            float ov = fsigmoid(p.w + xv.w);
            cc = fv * cc + iv * gv;
            float hval = ov * ftanh(cc);
            unsigned hbits = f2tf32(hval);
            hs[(wb * 8 + b) * HDP + jbase + jl] = hbits;   // local store
            if (STORE_OUT)
                out[((size_t)(bglob0 + b) * T + t) * HD + jbase + jl] =
                    __uint_as_float(hbits);
            if (hfin && t == T - 1)
                hfin[(size_t)(bglob0 + b) * HD + jbase + jl] = __uint_as_float(hbits);
        }
        __syncthreads();

        // ---- cooperative float4 broadcast of own slice to 7 peers ----
        for (int i = tid; i < CPY; i += NT) {
            int pr  = i / (8 * NG);
            int rem = i - pr * (8 * NG);
            int bb  = rem / NG;
            int k4  = rem - bb * NG;
            pr += (pr >= (int)rank);   // skip self
            uint32_t laddr = hs_base +
                4u * (uint32_t)((wb * 8 + bb) * HDP + jbase + 4 * k4);
            uint32_t raddr;
            asm("mapa.shared::cluster.u32 %0, %1, %2;"
                : "=r"(raddr) : "r"(laddr), "r"(pr));
            float4 v;
            asm volatile("ld.shared.v4.f32 {%0,%1,%2,%3}, [%4];"
                         : "=f"(v.x), "=f"(v.y), "=f"(v.z), "=f"(v.w)
                         : "r"(laddr));
            asm volatile("st.shared::cluster.v4.f32 [%0], {%1,%2,%3,%4};"
                         :: "r"(raddr), "f"(v.x), "f"(v.y), "f"(v.z), "f"(v.w)
                         : "memory");
        }

        CLUSTER_ARRIVE();
        if (t + 1 < T)   // prefetch next step's gates under barrier skew
            xv = *(const float4*)(xgp + (size_t)(t + 1) * (4 * HD));
        CLUSTER_WAIT();
    }
}

// ---------------- FC head ----------------
__global__ void fc_head(const float* __restrict__ h2,     // [64][128]
                        const float* __restrict__ Wfc,    // [64][128]
                        const float* __restrict__ bfc,    // [64]
                        const float* __restrict__ Wout,   // [1][64]
                        const float* __restrict__ bout,   // [1]
                        float* __restrict__ outp)         // [64]
{
    int b = threadIdx.x;  // 64 threads
    const float* hr = h2 + b * 128;
    float acc = 0.f;
    for (int uu = 0; uu < 64; uu++) {
        const float* wr = Wfc + uu * 128;
        float s0 = 0.f, s1 = 0.f, s2 = 0.f, s3 = 0.f;
#pragma unroll 8
        for (int k = 0; k < 128; k += 4) {
            s0 += hr[k]     * wr[k];
            s1 += hr[k + 1] * wr[k + 1];
            s2 += hr[k + 2] * wr[k + 2];
            s3 += hr[k + 3] * wr[k + 3];
        }
        float s = (s0 + s1) + (s2 + s3) + bfc[uu];
        acc += fmaxf(s, 0.f) * Wout[uu];
    }
    outp[b] = acc + bout[0];
}

// ---------------- launch ----------------
extern "C" void kernel_launch(void* const* d_in, const int* in_sizes, int n_in,
                              void* d_out, int out_size)
{
    const float* x    = (const float*)d_in[0];
    const float* Wih1 = (const float*)d_in[1];
    const float* Whh1 = (const float*)d_in[2];
    const float* bih1 = (const float*)d_in[3];
    const float* bhh1 = (const float*)d_in[4];
    const float* Wih2 = (const float*)d_in[5];
    const float* Whh2 = (const float*)d_in[6];
    const float* bih2 = (const float*)d_in[7];
    const float* bhh2 = (const float*)d_in[8];
    const float* Wfc1 = (const float*)d_in[9];
    const float* bfc1 = (const float*)d_in[10];
    const float* Wout = (const float*)d_in[11];
    const float* bout = (const float*)d_in[12];
    float* outp = (float*)d_out;

    float *xg1, *out1, *xg2, *w1cv, *w2cv, *h2f;
    cudaGetSymbolAddress((void**)&xg1,  g_xg1);
    cudaGetSymbolAddress((void**)&out1, g_out1);
    cudaGetSymbolAddress((void**)&xg2,  g_xg2);
    cudaGetSymbolAddress((void**)&w1cv, g_w1cv);
    cudaGetSymbolAddress((void**)&w2cv, g_w2cv);
    cudaGetSymbolAddress((void**)&h2f,  g_h2f);

    const int GEMM_SMEM = 2 * 128 * 36 * 4 * 2;                    // 73728 B
    const int R1_SMEM = (2 * 8 * 260) * 4 + 8 * 132 * 4;           // 20864 B
    const int R2_SMEM = (2 * 8 * 132) * 4 + 8 * 68 * 4;            // 10624 B
    cudaFuncSetAttribute(gemm_tf32_perm,
                         cudaFuncAttributeMaxDynamicSharedMemorySize, GEMM_SMEM);
    cudaFuncSetAttribute(lstm_recur_cl2<256, 32, 256, true>,
                         cudaFuncAttributeMaxDynamicSharedMemorySize, 64 * 1024);
    cudaFuncSetAttribute(lstm_recur_cl2<128, 16, 128, false>,
                         cudaFuncAttributeMaxDynamicSharedMemorySize, 64 * 1024);

    // prep: round input-projection weights to tf32
    cvt_rna_kernel<<<(1024 * 2048 + 255) / 256, 256>>>(Wih1, w1cv, 1024 * 2048);
    cvt_rna_kernel<<<(512 * 256 + 255) / 256, 256>>>(Wih2, w2cv, 512 * 256);

    const int M = 64 * 512;

    // layer 1 input projection
    gemm_tf32_perm<<<dim3(1024 / 128, M / 128), 256, GEMM_SMEM>>>(
        x, w1cv, bih1, bhh1, xg1, M, 1024, 2048);

    // layer 1 recurrence: 8 batch-groups x 8-CTA clusters
    lstm_recur_cl2<256, 32, 256, true><<<64, 256, R1_SMEM>>>(
        xg1, Whh1, out1, (float*)0, 512);

    // layer 2 input projection
    gemm_tf32_perm<<<dim3(512 / 128, M / 128), 256, GEMM_SMEM>>>(
        out1, w2cv, bih2, bhh2, xg2, M, 512, 256);

    // layer 2 recurrence
    lstm_recur_cl2<128, 16, 128, false><<<64, 128, R2_SMEM>>>(
        xg2, Whh2, (float*)0, h2f, 512);

    // FC head
    fc_head<<<1, 64>>>(h2f, Wfc1, bfc1, Wout, bout, outp);
}